// round 1
// baseline (speedup 1.0000x reference)
#include <cuda_runtime.h>
#include <math.h>

#define N_  4
#define T_  4096
#define D_  1024
#define H_  1536
#define M_  (N_*T_)       // 16384 rows
#define G2H (2*H_)        // 3072
#define TC  256           // scan chunk length
#define NC  (T_/TC)       // 16 chunks

// -------- scratch (device globals; no allocation allowed) --------
__device__ float g_gx  [(size_t)M_*G2H];   // x @ W_in^T ; gate half becomes gelu(gate) in-place
__device__ float g_xbc [(size_t)M_*H_];    // conv output
__device__ float g_fg  [(size_t)M_*G2H];   // xbc @ W_g^T + b_g
__device__ float g_alpha[(size_t)M_*H_];
__device__ float g_xs  [(size_t)M_*H_];    // xs, then overwritten with gelu(gate)*h in scan p3
__device__ float g_cA  [N_*NC*H_];
__device__ float g_cB  [N_*NC*H_];

// -------- generic NT GEMM: C[M,Nn] = A[M,K] * B[Nn,K]^T (+bias) --------
// 128x128 block tile, BK=8, 256 threads, 8x8 per thread. All dims divisible.
template<bool HAS_BIAS>
__global__ __launch_bounds__(256)
void gemm_nt(const float* __restrict__ A, const float* __restrict__ B,
             const float* __restrict__ bias, float* __restrict__ C,
             int K, int lda, int ldb, int ldc)
{
    __shared__ float As[8][128];
    __shared__ float Bs[8][128];
    const int tid = threadIdx.x;
    const int bm = blockIdx.y * 128;
    const int bn = blockIdx.x * 128;
    const int lr = tid >> 1;          // row within tile [0,128)
    const int lc = (tid & 1) * 4;     // k offset {0,4}
    const int ty = tid >> 4;          // [0,16)
    const int tx = tid & 15;          // [0,16)

    const float* Ap = A + (size_t)(bm + lr) * lda + lc;
    const float* Bp = B + (size_t)(bn + lr) * ldb + lc;

    float acc[8][8];
#pragma unroll
    for (int i = 0; i < 8; i++)
#pragma unroll
        for (int j = 0; j < 8; j++) acc[i][j] = 0.f;

    for (int k0 = 0; k0 < K; k0 += 8) {
        float4 av = *(const float4*)(Ap + k0);
        float4 bv = *(const float4*)(Bp + k0);
        __syncthreads();
        As[lc+0][lr] = av.x; As[lc+1][lr] = av.y; As[lc+2][lr] = av.z; As[lc+3][lr] = av.w;
        Bs[lc+0][lr] = bv.x; Bs[lc+1][lr] = bv.y; Bs[lc+2][lr] = bv.z; Bs[lc+3][lr] = bv.w;
        __syncthreads();
#pragma unroll
        for (int kk = 0; kk < 8; kk++) {
            float a[8], b[8];
            *(float4*)(a)   = *(const float4*)(&As[kk][ty*8]);
            *(float4*)(a+4) = *(const float4*)(&As[kk][ty*8+4]);
            *(float4*)(b)   = *(const float4*)(&Bs[kk][tx*8]);
            *(float4*)(b+4) = *(const float4*)(&Bs[kk][tx*8+4]);
#pragma unroll
            for (int i = 0; i < 8; i++)
#pragma unroll
                for (int j = 0; j < 8; j++)
                    acc[i][j] = fmaf(a[i], b[j], acc[i][j]);
        }
    }

#pragma unroll
    for (int i = 0; i < 8; i++) {
        const size_t row = (size_t)(bm + ty*8 + i);
#pragma unroll
        for (int j = 0; j < 8; j++) {
            const int col = bn + tx*8 + j;
            float v = acc[i][j];
            if (HAS_BIAS) v += bias[col];
            C[row * ldc + col] = v;
        }
    }
}

// -------- depthwise causal conv K=4 over t; reads B-half of g_gx --------
__global__ void conv_kernel(const float* __restrict__ cw, const float* __restrict__ cb)
{
    long long idx = (long long)blockIdx.x * blockDim.x + threadIdx.x;
    if (idx >= (long long)M_ * H_) return;
    int h = (int)(idx % H_);
    long long m = idx / H_;
    int t = (int)(m % T_);
    long long n = m / T_;
    float acc = cb[h];
    const float* w = cw + h * 4;
#pragma unroll
    for (int k = 0; k < 4; k++) {
        int tt = t - 3 + k;
        if (tt >= 0)
            acc = fmaf(w[k], g_gx[((size_t)(n * T_ + tt)) * G2H + H_ + h], acc);
    }
    g_xbc[idx] = acc;
}

// -------- elementwise: alpha, xs, and gelu(gate) in place --------
__device__ __forceinline__ float sigmoidf_(float v) { return 1.f / (1.f + expf(-v)); }

__global__ void ew_kernel(const float* __restrict__ fb_arr)
{
    long long idx = (long long)blockIdx.x * blockDim.x + threadIdx.x;
    if (idx >= (long long)M_ * H_) return;
    int h = (int)(idx % H_);
    size_t m = (size_t)(idx / H_);

    float forget = g_fg[m * G2H + h];
    float inp    = g_fg[m * G2H + H_ + h];
    float fb     = fb_arr[h];
    float sp     = fmaxf(fb, 0.f) + log1pf(expf(-fabsf(fb)));   // stable softplus
    float a      = expf(-8.f * sp * sigmoidf_(forget));
    float beta   = sqrtf(1.f - a * a + 1e-6f);
    float xb     = g_xbc[idx];
    g_alpha[idx] = a;
    g_xs[idx]    = beta * sigmoidf_(inp) * xb;

    // gelu(gate) in place (exact gelu)
    float g = g_gx[m * G2H + h];
    g_gx[m * G2H + h] = 0.5f * g * (1.f + erff(g * 0.70710678118654752f));
}

// -------- chunked linear scan: h_t = a_t * h_{t-1} + x_t --------
__global__ void scan_p1()   // per-chunk (prodA, local B)
{
    int h = blockIdx.x * 128 + threadIdx.x;
    int c = blockIdx.y, n = blockIdx.z;
    size_t base = ((size_t)(n * T_ + c * TC)) * H_ + h;
    float A = 1.f, Bv = 0.f;
#pragma unroll 4
    for (int t = 0; t < TC; t++) {
        float a = g_alpha[base + (size_t)t * H_];
        float x = g_xs   [base + (size_t)t * H_];
        Bv = fmaf(a, Bv, x);
        A *= a;
    }
    int ci = (n * NC + c) * H_ + h;
    g_cA[ci] = A;
    g_cB[ci] = Bv;
}

__global__ void scan_p2()   // scan carries over chunks; g_cB becomes carry-in
{
    int h = blockIdx.x * 128 + threadIdx.x;
    int n = blockIdx.y;
    float carry = 0.f;
    for (int c = 0; c < NC; c++) {
        int i = (n * NC + c) * H_ + h;
        float a = g_cA[i], b = g_cB[i];
        g_cB[i] = carry;
        carry = fmaf(a, carry, b);
    }
}

__global__ void scan_p3()   // replay with carry; write gelu(gate)*h over g_xs
{
    int h = blockIdx.x * 128 + threadIdx.x;
    int c = blockIdx.y, n = blockIdx.z;
    size_t base  = ((size_t)(n * T_ + c * TC)) * H_ + h;
    size_t gbase = ((size_t)(n * T_ + c * TC)) * G2H + h;
    float hp = g_cB[(n * NC + c) * H_ + h];
#pragma unroll 4
    for (int t = 0; t < TC; t++) {
        float a = g_alpha[base + (size_t)t * H_];
        float x = g_xs   [base + (size_t)t * H_];
        hp = fmaf(a, hp, x);
        float g = g_gx[gbase + (size_t)t * G2H];   // gelu(gate)
        g_xs[base + (size_t)t * H_] = hp * g;
    }
}

// -------- launch --------
extern "C" void kernel_launch(void* const* d_in, const int* in_sizes, int n_in,
                              void* d_out, int out_size)
{
    const float* x      = (const float*)d_in[0];
    const float* W_in   = (const float*)d_in[1];
    const float* conv_w = (const float*)d_in[2];
    const float* conv_b = (const float*)d_in[3];
    const float* W_g    = (const float*)d_in[4];
    const float* b_g    = (const float*)d_in[5];
    const float* fbase  = (const float*)d_in[6];
    const float* W_out  = (const float*)d_in[7];
    float* out = (float*)d_out;

    float *gx, *xbc, *fg, *xs;
    cudaGetSymbolAddress((void**)&gx,  g_gx);
    cudaGetSymbolAddress((void**)&xbc, g_xbc);
    cudaGetSymbolAddress((void**)&fg,  g_fg);
    cudaGetSymbolAddress((void**)&xs,  g_xs);

    const long long tot = (long long)M_ * H_;
    const int EB = 256;
    const int eg = (int)((tot + EB - 1) / EB);

    // 1) gx = x @ W_in^T
    gemm_nt<false><<<dim3(G2H/128, M_/128), 256>>>(x, W_in, nullptr, gx, D_, D_, D_, G2H);
    // 2) depthwise causal conv on B-half
    conv_kernel<<<eg, EB>>>(conv_w, conv_b);
    // 3) fg = xbc @ W_g^T + b_g
    gemm_nt<true><<<dim3(G2H/128, M_/128), 256>>>(xbc, W_g, b_g, fg, H_, H_, H_, G2H);
    // 4) alpha/xs + gelu(gate) in place
    ew_kernel<<<eg, EB>>>(fbase);
    // 5) linear scan (3 phases), p3 fuses gelu(gate)*h into g_xs
    scan_p1<<<dim3(H_/128, NC, N_), 128>>>();
    scan_p2<<<dim3(H_/128, N_), 128>>>();
    scan_p3<<<dim3(H_/128, NC, N_), 128>>>();
    // 6) out = (gelu(gate)*h) @ W_out^T
    gemm_nt<false><<<dim3(D_/128, M_/128), 256>>>(xs, W_out, nullptr, out, H_, H_, H_, D_);
}

// round 3
// speedup vs baseline: 2.6672x; 2.6672x over previous
#include <cuda_runtime.h>
#include <cuda_bf16.h>
#include <math.h>
#include <stdint.h>

#define N_  4
#define T_  4096
#define D_  1024
#define H_  1536
#define M_  (N_*T_)       // 16384 rows
#define G2H (2*H_)        // 3072
#define TC  256           // scan chunk length
#define NC  (T_/TC)       // 16 chunks

// -------- scratch (device globals; no allocation allowed) --------
__device__ float g_gx  [(size_t)M_*G2H];   // x @ W_in^T ; gate half becomes gelu(gate) in-place
__device__ float g_xbc [(size_t)M_*H_];    // conv output
__device__ float g_fg  [(size_t)M_*G2H];   // xbc @ W_g^T + b_g
__device__ float g_alpha[(size_t)M_*H_];
__device__ float g_xs  [(size_t)M_*H_];    // xs, then overwritten with gelu(gate)*h in scan p3
__device__ float g_cA  [N_*NC*H_];
__device__ float g_cB  [N_*NC*H_];

// ======================= mma.sync helpers =======================
__device__ __forceinline__ uint32_t smem_u32(const void* p) {
    uint32_t a;
    asm("{ .reg .u64 t; cvta.to.shared.u64 t, %1; cvt.u32.u64 %0, t; }" : "=r"(a) : "l"(p));
    return a;
}
__device__ __forceinline__ void ldmx4(uint32_t* r, uint32_t a) {
    asm volatile("ldmatrix.sync.aligned.m8n8.x4.shared.b16 {%0,%1,%2,%3}, [%4];"
        : "=r"(r[0]), "=r"(r[1]), "=r"(r[2]), "=r"(r[3]) : "r"(a));
}
__device__ __forceinline__ void mma16816(float* d, const uint32_t* a, const uint32_t* b) {
    asm volatile("mma.sync.aligned.m16n8k16.row.col.f32.bf16.bf16.f32 "
        "{%0,%1,%2,%3}, {%4,%5,%6,%7}, {%8,%9}, {%0,%1,%2,%3};"
        : "+f"(d[0]), "+f"(d[1]), "+f"(d[2]), "+f"(d[3])
        : "r"(a[0]), "r"(a[1]), "r"(a[2]), "r"(a[3]), "r"(b[0]), "r"(b[1]));
}

// ================== bf16x3 mma.sync GEMM: C[M,Nn]=A[M,K]*B[Nn,K]^T ==================
// Block tile 128x128x32, 256 threads (8 warps: 4(m) x 2(n)), warp tile 32x64.
// SMEM rows padded to 80B (32 bf16 + 8 pad) -> ldmatrix conflict-free.
#define BKB    80          // bytes per smem row (32 bf16 + 16B pad)
#define AH_OFF 0
#define AL_OFF 10240
#define BH_OFF 20480
#define BL_OFF 30720
#define STAGE  40960
#define GEMM_SMEM (2*STAGE)   // 81920

__device__ __forceinline__ void load_f4(const float* g, int ld, int tid, float4* r) {
#pragma unroll
    for (int i = 0; i < 4; i++) {
        int idx = i * 256 + tid;
        int row = idx >> 3, c4 = idx & 7;
        r[i] = *(const float4*)(g + (size_t)row * ld + c4 * 4);
    }
}
__device__ __forceinline__ void store_split(char* hi, char* lo, int tid, const float4* r) {
#pragma unroll
    for (int i = 0; i < 4; i++) {
        int idx = i * 256 + tid;
        int row = idx >> 3, c4 = idx & 7;
        float4 f = r[i];
        __nv_bfloat162 h0 = __floats2bfloat162_rn(f.x, f.y);
        __nv_bfloat162 h1 = __floats2bfloat162_rn(f.z, f.w);
        float2 r0 = __bfloat1622float2(h0);
        float2 r1 = __bfloat1622float2(h1);
        __nv_bfloat162 l0 = __floats2bfloat162_rn(f.x - r0.x, f.y - r0.y);
        __nv_bfloat162 l1 = __floats2bfloat162_rn(f.z - r1.x, f.w - r1.y);
        uint32_t off = (uint32_t)(row * BKB + c4 * 8);
        uint2 hv, lv;
        hv.x = *(uint32_t*)&h0; hv.y = *(uint32_t*)&h1;
        lv.x = *(uint32_t*)&l0; lv.y = *(uint32_t*)&l1;
        *(uint2*)(hi + off) = hv;
        *(uint2*)(lo + off) = lv;
    }
}

template<bool HAS_BIAS>
__global__ __launch_bounds__(256)
void gemm_mma(const float* __restrict__ A, const float* __restrict__ B,
              const float* __restrict__ bias, float* __restrict__ C,
              int K, int lda, int ldb, int ldc)
{
    extern __shared__ char sm[];
    const int tid = threadIdx.x;
    const int lid = tid & 31, wid = tid >> 5;
    const int wm = wid >> 1, wn = wid & 1;   // 4 x 2 warp grid
    const int bm = blockIdx.y * 128;
    const int bn = blockIdx.x * 128;

    const float* Ag = A + (size_t)bm * lda;
    const float* Bg = B + (size_t)bn * ldb;

    float acc[2][8][4];
#pragma unroll
    for (int i = 0; i < 2; i++)
#pragma unroll
        for (int j = 0; j < 8; j++)
#pragma unroll
            for (int q = 0; q < 4; q++) acc[i][j][q] = 0.f;

    float4 ra[4], rb[4];
    load_f4(Ag, lda, tid, ra);
    load_f4(Bg, ldb, tid, rb);
    store_split(sm + AH_OFF, sm + AL_OFF, tid, ra);
    store_split(sm + BH_OFF, sm + BL_OFF, tid, rb);
    __syncthreads();

    const uint32_t sb = smem_u32(sm);
    // ldmatrix lane address bases
    const uint32_t a_base = sb + (uint32_t)((wm * 32 + (lid & 15)) * BKB + ((lid >> 4) & 1) * 16);
    const uint32_t b_base = sb + BH_OFF +
        (uint32_t)((wn * 64 + (lid & 7) + ((lid >> 4) & 1) * 8) * BKB + ((lid >> 3) & 1) * 16);

    const int KT = K >> 5;
    for (int c = 0; c < KT; c++) {
        const int cur = c & 1;
        const bool more = (c + 1 < KT);
        if (more) {
            load_f4(Ag + (c + 1) * 32, lda, tid, ra);
            load_f4(Bg + (c + 1) * 32, ldb, tid, rb);
        }
        const uint32_t sa  = a_base + cur * STAGE;
        const uint32_t sbb = b_base + cur * STAGE;
#pragma unroll
        for (int kt = 0; kt < 2; kt++) {
            uint32_t ah[2][4], al[2][4], bh[4][4], bl[4][4];
#pragma unroll
            for (int mt = 0; mt < 2; mt++) {
                ldmx4(ah[mt], sa + mt * (16 * BKB) + kt * 32);
                ldmx4(al[mt], sa + AL_OFF + mt * (16 * BKB) + kt * 32);
            }
#pragma unroll
            for (int n2 = 0; n2 < 4; n2++) {
                ldmx4(bh[n2], sbb + n2 * (16 * BKB) + kt * 32);
                ldmx4(bl[n2], sbb + (BL_OFF - BH_OFF) + n2 * (16 * BKB) + kt * 32);
            }
#pragma unroll
            for (int mt = 0; mt < 2; mt++)
#pragma unroll
                for (int nt = 0; nt < 8; nt++) {
                    uint32_t* bph = &bh[nt >> 1][(nt & 1) * 2];
                    uint32_t* bpl = &bl[nt >> 1][(nt & 1) * 2];
                    mma16816(acc[mt][nt], ah[mt], bph);
                    mma16816(acc[mt][nt], ah[mt], bpl);
                    mma16816(acc[mt][nt], al[mt], bph);
                }
        }
        if (more) {
            const int nxt = (c + 1) & 1;
            store_split(sm + nxt * STAGE + AH_OFF, sm + nxt * STAGE + AL_OFF, tid, ra);
            store_split(sm + nxt * STAGE + BH_OFF, sm + nxt * STAGE + BL_OFF, tid, rb);
        }
        __syncthreads();
    }

    // epilogue: direct register -> global (float2 per row segment, sector-aligned)
    const int r0 = bm + wm * 32 + (lid >> 2);
    const int cbase = bn + wn * 64 + (lid & 3) * 2;
#pragma unroll
    for (int mt = 0; mt < 2; mt++) {
        const int row = r0 + mt * 16;
#pragma unroll
        for (int nt = 0; nt < 8; nt++) {
            const int col = cbase + nt * 8;
            float2 v0 = make_float2(acc[mt][nt][0], acc[mt][nt][1]);
            float2 v1 = make_float2(acc[mt][nt][2], acc[mt][nt][3]);
            if (HAS_BIAS) {
                float2 bv = *(const float2*)(bias + col);
                v0.x += bv.x; v0.y += bv.y; v1.x += bv.x; v1.y += bv.y;
            }
            *(float2*)(C + (size_t)row * ldc + col) = v0;
            *(float2*)(C + (size_t)(row + 8) * ldc + col) = v1;
        }
    }
}

// -------- depthwise causal conv K=4 over t; reads B-half of g_gx --------
__global__ void conv_kernel(const float* __restrict__ cw, const float* __restrict__ cb)
{
    long long idx = (long long)blockIdx.x * blockDim.x + threadIdx.x;
    if (idx >= (long long)M_ * H_) return;
    int h = (int)(idx % H_);
    long long m = idx / H_;
    int t = (int)(m % T_);
    long long n = m / T_;
    float acc = cb[h];
    const float* w = cw + h * 4;
#pragma unroll
    for (int k = 0; k < 4; k++) {
        int tt = t - 3 + k;
        if (tt >= 0)
            acc = fmaf(w[k], g_gx[((size_t)(n * T_ + tt)) * G2H + H_ + h], acc);
    }
    g_xbc[idx] = acc;
}

// -------- elementwise: alpha, xs, and gelu(gate) in place --------
__device__ __forceinline__ float sigmoidf_(float v) { return 1.f / (1.f + expf(-v)); }

__global__ void ew_kernel(const float* __restrict__ fb_arr)
{
    long long idx = (long long)blockIdx.x * blockDim.x + threadIdx.x;
    if (idx >= (long long)M_ * H_) return;
    int h = (int)(idx % H_);
    size_t m = (size_t)(idx / H_);

    float forget = g_fg[m * G2H + h];
    float inp    = g_fg[m * G2H + H_ + h];
    float fb     = fb_arr[h];
    float sp     = fmaxf(fb, 0.f) + log1pf(expf(-fabsf(fb)));   // stable softplus
    float a      = expf(-8.f * sp * sigmoidf_(forget));
    float beta   = sqrtf(1.f - a * a + 1e-6f);
    float xb     = g_xbc[idx];
    g_alpha[idx] = a;
    g_xs[idx]    = beta * sigmoidf_(inp) * xb;

    float g = g_gx[m * G2H + h];
    g_gx[m * G2H + h] = 0.5f * g * (1.f + erff(g * 0.70710678118654752f));
}

// -------- chunked linear scan: h_t = a_t * h_{t-1} + x_t --------
__global__ void scan_p1()
{
    int h = blockIdx.x * 128 + threadIdx.x;
    int c = blockIdx.y, n = blockIdx.z;
    size_t base = ((size_t)(n * T_ + c * TC)) * H_ + h;
    float A = 1.f, Bv = 0.f;
#pragma unroll 4
    for (int t = 0; t < TC; t++) {
        float a = g_alpha[base + (size_t)t * H_];
        float x = g_xs   [base + (size_t)t * H_];
        Bv = fmaf(a, Bv, x);
        A *= a;
    }
    int ci = (n * NC + c) * H_ + h;
    g_cA[ci] = A;
    g_cB[ci] = Bv;
}

__global__ void scan_p2()
{
    int h = blockIdx.x * 128 + threadIdx.x;
    int n = blockIdx.y;
    float carry = 0.f;
    for (int c = 0; c < NC; c++) {
        int i = (n * NC + c) * H_ + h;
        float a = g_cA[i], b = g_cB[i];
        g_cB[i] = carry;
        carry = fmaf(a, carry, b);
    }
}

__global__ void scan_p3()
{
    int h = blockIdx.x * 128 + threadIdx.x;
    int c = blockIdx.y, n = blockIdx.z;
    size_t base  = ((size_t)(n * T_ + c * TC)) * H_ + h;
    size_t gbase = ((size_t)(n * T_ + c * TC)) * G2H + h;
    float hp = g_cB[(n * NC + c) * H_ + h];
#pragma unroll 4
    for (int t = 0; t < TC; t++) {
        float a = g_alpha[base + (size_t)t * H_];
        float x = g_xs   [base + (size_t)t * H_];
        hp = fmaf(a, hp, x);
        float g = g_gx[gbase + (size_t)t * G2H];
        g_xs[base + (size_t)t * H_] = hp * g;
    }
}

// -------- launch --------
extern "C" void kernel_launch(void* const* d_in, const int* in_sizes, int n_in,
                              void* d_out, int out_size)
{
    const float* x      = (const float*)d_in[0];
    const float* W_in   = (const float*)d_in[1];
    const float* conv_w = (const float*)d_in[2];
    const float* conv_b = (const float*)d_in[3];
    const float* W_g    = (const float*)d_in[4];
    const float* b_g    = (const float*)d_in[5];
    const float* fbase  = (const float*)d_in[6];
    const float* W_out  = (const float*)d_in[7];
    float* out = (float*)d_out;

    float *gx, *xbc, *fg, *xs;
    cudaGetSymbolAddress((void**)&gx,  g_gx);
    cudaGetSymbolAddress((void**)&xbc, g_xbc);
    cudaGetSymbolAddress((void**)&fg,  g_fg);
    cudaGetSymbolAddress((void**)&xs,  g_xs);

    cudaFuncSetAttribute(gemm_mma<false>, cudaFuncAttributeMaxDynamicSharedMemorySize, GEMM_SMEM);
    cudaFuncSetAttribute(gemm_mma<true>,  cudaFuncAttributeMaxDynamicSharedMemorySize, GEMM_SMEM);

    const long long tot = (long long)M_ * H_;
    const int EB = 256;
    const int eg = (int)((tot + EB - 1) / EB);

    // 1) gx = x @ W_in^T      [16384 x 3072, K=1024]
    gemm_mma<false><<<dim3(G2H/128, M_/128), 256, GEMM_SMEM>>>(x, W_in, nullptr, gx, D_, D_, D_, G2H);
    // 2) depthwise causal conv on B-half
    conv_kernel<<<eg, EB>>>(conv_w, conv_b);
    // 3) fg = xbc @ W_g^T + b_g   [16384 x 3072, K=1536]
    gemm_mma<true><<<dim3(G2H/128, M_/128), 256, GEMM_SMEM>>>(xbc, W_g, b_g, fg, H_, H_, H_, G2H);
    // 4) alpha/xs + gelu(gate)
    ew_kernel<<<eg, EB>>>(fbase);
    // 5) linear scan (3 phases)
    scan_p1<<<dim3(H_/128, NC, N_), 128>>>();
    scan_p2<<<dim3(H_/128, N_), 128>>>();
    scan_p3<<<dim3(H_/128, NC, N_), 128>>>();
    // 6) out = (gelu(gate)*h) @ W_out^T   [16384 x 1024, K=1536]
    gemm_mma<false><<<dim3(D_/128, M_/128), 256, GEMM_SMEM>>>(xs, W_out, nullptr, out, H_, H_, H_, D_);
}

// round 4
// speedup vs baseline: 2.6713x; 1.0016x over previous
#include <cuda_runtime.h>
#include <cuda_bf16.h>
#include <math.h>
#include <stdint.h>

#define N_  4
#define T_  4096
#define D_  1024
#define H_  1536
#define M_  (N_*T_)       // 16384 rows
#define G2H (2*H_)        // 3072
#define TC  256           // scan chunk length
#define NC  (T_/TC)       // 16 chunks

// -------- scratch (device globals; no allocation allowed) --------
__device__ float g_gx  [(size_t)M_*G2H];   // x @ W_in^T ; gate half becomes gelu(gate) in-place
__device__ float g_xbc [(size_t)M_*H_];    // conv output
__device__ float g_fg  [(size_t)M_*G2H];   // xbc @ W_g^T + b_g
__device__ float g_alpha[(size_t)M_*H_];
__device__ float g_xs  [(size_t)M_*H_];    // xs, then overwritten with gelu(gate)*h in scan p3
__device__ float g_cA  [N_*NC*H_];
__device__ float g_cB  [N_*NC*H_];

// ======================= mma.sync helpers =======================
__device__ __forceinline__ uint32_t smem_u32(const void* p) {
    uint32_t a;
    asm("{ .reg .u64 t; cvta.to.shared.u64 t, %1; cvt.u32.u64 %0, t; }" : "=r"(a) : "l"(p));
    return a;
}
__device__ __forceinline__ void ldmx4(uint32_t* r, uint32_t a) {
    asm volatile("ldmatrix.sync.aligned.m8n8.x4.shared.b16 {%0,%1,%2,%3}, [%4];"
        : "=r"(r[0]), "=r"(r[1]), "=r"(r[2]), "=r"(r[3]) : "r"(a));
}
__device__ __forceinline__ void mma16816(float* d, const uint32_t* a, const uint32_t* b) {
    asm volatile("mma.sync.aligned.m16n8k16.row.col.f32.bf16.bf16.f32 "
        "{%0,%1,%2,%3}, {%4,%5,%6,%7}, {%8,%9}, {%0,%1,%2,%3};"
        : "+f"(d[0]), "+f"(d[1]), "+f"(d[2]), "+f"(d[3])
        : "r"(a[0]), "r"(a[1]), "r"(a[2]), "r"(a[3]), "r"(b[0]), "r"(b[1]));
}

// ================== bf16x3 mma.sync GEMM: C[M,Nn]=A[M,K]*B[Nn,K]^T ==================
// Block tile 128x128x32, 256 threads (8 warps: 4(m) x 2(n)), warp tile 32x64.
// SMEM rows padded to 80B (32 bf16 + 8 pad) -> ldmatrix conflict-free.
#define BKB    80          // bytes per smem row (32 bf16 + 16B pad)
#define AH_OFF 0
#define AL_OFF 10240
#define BH_OFF 20480
#define BL_OFF 30720
#define STAGE  40960
#define GEMM_SMEM (2*STAGE)   // 81920

__device__ __forceinline__ void load_f4(const float* g, int ld, int tid, float4* r) {
#pragma unroll
    for (int i = 0; i < 4; i++) {
        int idx = i * 256 + tid;
        int row = idx >> 3, c4 = idx & 7;
        r[i] = *(const float4*)(g + (size_t)row * ld + c4 * 4);
    }
}
__device__ __forceinline__ void store_split(char* hi, char* lo, int tid, const float4* r) {
#pragma unroll
    for (int i = 0; i < 4; i++) {
        int idx = i * 256 + tid;
        int row = idx >> 3, c4 = idx & 7;
        float4 f = r[i];
        __nv_bfloat162 h0 = __floats2bfloat162_rn(f.x, f.y);
        __nv_bfloat162 h1 = __floats2bfloat162_rn(f.z, f.w);
        float2 r0 = __bfloat1622float2(h0);
        float2 r1 = __bfloat1622float2(h1);
        __nv_bfloat162 l0 = __floats2bfloat162_rn(f.x - r0.x, f.y - r0.y);
        __nv_bfloat162 l1 = __floats2bfloat162_rn(f.z - r1.x, f.w - r1.y);
        uint32_t off = (uint32_t)(row * BKB + c4 * 8);
        uint2 hv, lv;
        hv.x = *(uint32_t*)&h0; hv.y = *(uint32_t*)&h1;
        lv.x = *(uint32_t*)&l0; lv.y = *(uint32_t*)&l1;
        *(uint2*)(hi + off) = hv;
        *(uint2*)(lo + off) = lv;
    }
}

template<bool HAS_BIAS>
__global__ __launch_bounds__(256)
void gemm_mma(const float* __restrict__ A, const float* __restrict__ B,
              const float* __restrict__ bias, float* __restrict__ C,
              int K, int lda, int ldb, int ldc)
{
    extern __shared__ char sm[];
    const int tid = threadIdx.x;
    const int lid = tid & 31, wid = tid >> 5;
    const int wm = wid >> 1, wn = wid & 1;   // 4 x 2 warp grid
    const int bm = blockIdx.y * 128;
    const int bn = blockIdx.x * 128;

    const float* Ag = A + (size_t)bm * lda;
    const float* Bg = B + (size_t)bn * ldb;

    float acc[2][8][4];
#pragma unroll
    for (int i = 0; i < 2; i++)
#pragma unroll
        for (int j = 0; j < 8; j++)
#pragma unroll
            for (int q = 0; q < 4; q++) acc[i][j][q] = 0.f;

    float4 ra[4], rb[4];
    load_f4(Ag, lda, tid, ra);
    load_f4(Bg, ldb, tid, rb);
    store_split(sm + AH_OFF, sm + AL_OFF, tid, ra);
    store_split(sm + BH_OFF, sm + BL_OFF, tid, rb);
    __syncthreads();

    const uint32_t sb = smem_u32(sm);
    // ldmatrix lane address bases
    const uint32_t a_base = sb + (uint32_t)((wm * 32 + (lid & 15)) * BKB + ((lid >> 4) & 1) * 16);
    const uint32_t b_base = sb + BH_OFF +
        (uint32_t)((wn * 64 + (lid & 7) + ((lid >> 4) & 1) * 8) * BKB + ((lid >> 3) & 1) * 16);

    const int KT = K >> 5;
    for (int c = 0; c < KT; c++) {
        const int cur = c & 1;
        const bool more = (c + 1 < KT);
        if (more) {
            load_f4(Ag + (c + 1) * 32, lda, tid, ra);
            load_f4(Bg + (c + 1) * 32, ldb, tid, rb);
        }
        const uint32_t sa  = a_base + cur * STAGE;
        const uint32_t sbb = b_base + cur * STAGE;
#pragma unroll
        for (int kt = 0; kt < 2; kt++) {
            uint32_t ah[2][4], al[2][4], bh[4][4], bl[4][4];
#pragma unroll
            for (int mt = 0; mt < 2; mt++) {
                ldmx4(ah[mt], sa + mt * (16 * BKB) + kt * 32);
                ldmx4(al[mt], sa + AL_OFF + mt * (16 * BKB) + kt * 32);
            }
#pragma unroll
            for (int n2 = 0; n2 < 4; n2++) {
                ldmx4(bh[n2], sbb + n2 * (16 * BKB) + kt * 32);
                ldmx4(bl[n2], sbb + (BL_OFF - BH_OFF) + n2 * (16 * BKB) + kt * 32);
            }
#pragma unroll
            for (int mt = 0; mt < 2; mt++)
#pragma unroll
                for (int nt = 0; nt < 8; nt++) {
                    uint32_t* bph = &bh[nt >> 1][(nt & 1) * 2];
                    uint32_t* bpl = &bl[nt >> 1][(nt & 1) * 2];
                    mma16816(acc[mt][nt], ah[mt], bph);
                    mma16816(acc[mt][nt], ah[mt], bpl);
                    mma16816(acc[mt][nt], al[mt], bph);
                }
        }
        if (more) {
            const int nxt = (c + 1) & 1;
            store_split(sm + nxt * STAGE + AH_OFF, sm + nxt * STAGE + AL_OFF, tid, ra);
            store_split(sm + nxt * STAGE + BH_OFF, sm + nxt * STAGE + BL_OFF, tid, rb);
        }
        __syncthreads();
    }

    // epilogue: direct register -> global (float2 per row segment, sector-aligned)
    const int r0 = bm + wm * 32 + (lid >> 2);
    const int cbase = bn + wn * 64 + (lid & 3) * 2;
#pragma unroll
    for (int mt = 0; mt < 2; mt++) {
        const int row = r0 + mt * 16;
#pragma unroll
        for (int nt = 0; nt < 8; nt++) {
            const int col = cbase + nt * 8;
            float2 v0 = make_float2(acc[mt][nt][0], acc[mt][nt][1]);
            float2 v1 = make_float2(acc[mt][nt][2], acc[mt][nt][3]);
            if (HAS_BIAS) {
                float2 bv = *(const float2*)(bias + col);
                v0.x += bv.x; v0.y += bv.y; v1.x += bv.x; v1.y += bv.y;
            }
            *(float2*)(C + (size_t)row * ldc + col) = v0;
            *(float2*)(C + (size_t)(row + 8) * ldc + col) = v1;
        }
    }
}

// -------- depthwise causal conv K=4 over t; reads B-half of g_gx --------
__global__ void conv_kernel(const float* __restrict__ cw, const float* __restrict__ cb)
{
    long long idx = (long long)blockIdx.x * blockDim.x + threadIdx.x;
    if (idx >= (long long)M_ * H_) return;
    int h = (int)(idx % H_);
    long long m = idx / H_;
    int t = (int)(m % T_);
    long long n = m / T_;
    float acc = cb[h];
    const float* w = cw + h * 4;
#pragma unroll
    for (int k = 0; k < 4; k++) {
        int tt = t - 3 + k;
        if (tt >= 0)
            acc = fmaf(w[k], g_gx[((size_t)(n * T_ + tt)) * G2H + H_ + h], acc);
    }
    g_xbc[idx] = acc;
}

// -------- elementwise: alpha, xs, and gelu(gate) in place --------
__device__ __forceinline__ float sigmoidf_(float v) { return 1.f / (1.f + expf(-v)); }

__global__ void ew_kernel(const float* __restrict__ fb_arr)
{
    long long idx = (long long)blockIdx.x * blockDim.x + threadIdx.x;
    if (idx >= (long long)M_ * H_) return;
    int h = (int)(idx % H_);
    size_t m = (size_t)(idx / H_);

    float forget = g_fg[m * G2H + h];
    float inp    = g_fg[m * G2H + H_ + h];
    float fb     = fb_arr[h];
    float sp     = fmaxf(fb, 0.f) + log1pf(expf(-fabsf(fb)));   // stable softplus
    float a      = expf(-8.f * sp * sigmoidf_(forget));
    float beta   = sqrtf(1.f - a * a + 1e-6f);
    float xb     = g_xbc[idx];
    g_alpha[idx] = a;
    g_xs[idx]    = beta * sigmoidf_(inp) * xb;

    float g = g_gx[m * G2H + h];
    g_gx[m * G2H + h] = 0.5f * g * (1.f + erff(g * 0.70710678118654752f));
}

// -------- chunked linear scan: h_t = a_t * h_{t-1} + x_t --------
__global__ void scan_p1()
{
    int h = blockIdx.x * 128 + threadIdx.x;
    int c = blockIdx.y, n = blockIdx.z;
    size_t base = ((size_t)(n * T_ + c * TC)) * H_ + h;
    float A = 1.f, Bv = 0.f;
#pragma unroll 4
    for (int t = 0; t < TC; t++) {
        float a = g_alpha[base + (size_t)t * H_];
        float x = g_xs   [base + (size_t)t * H_];
        Bv = fmaf(a, Bv, x);
        A *= a;
    }
    int ci = (n * NC + c) * H_ + h;
    g_cA[ci] = A;
    g_cB[ci] = Bv;
}

__global__ void scan_p2()
{
    int h = blockIdx.x * 128 + threadIdx.x;
    int n = blockIdx.y;
    float carry = 0.f;
    for (int c = 0; c < NC; c++) {
        int i = (n * NC + c) * H_ + h;
        float a = g_cA[i], b = g_cB[i];
        g_cB[i] = carry;
        carry = fmaf(a, carry, b);
    }
}

__global__ void scan_p3()
{
    int h = blockIdx.x * 128 + threadIdx.x;
    int c = blockIdx.y, n = blockIdx.z;
    size_t base  = ((size_t)(n * T_ + c * TC)) * H_ + h;
    size_t gbase = ((size_t)(n * T_ + c * TC)) * G2H + h;
    float hp = g_cB[(n * NC + c) * H_ + h];
#pragma unroll 4
    for (int t = 0; t < TC; t++) {
        float a = g_alpha[base + (size_t)t * H_];
        float x = g_xs   [base + (size_t)t * H_];
        hp = fmaf(a, hp, x);
        float g = g_gx[gbase + (size_t)t * G2H];
        g_xs[base + (size_t)t * H_] = hp * g;
    }
}

// -------- launch --------
extern "C" void kernel_launch(void* const* d_in, const int* in_sizes, int n_in,
                              void* d_out, int out_size)
{
    const float* x      = (const float*)d_in[0];
    const float* W_in   = (const float*)d_in[1];
    const float* conv_w = (const float*)d_in[2];
    const float* conv_b = (const float*)d_in[3];
    const float* W_g    = (const float*)d_in[4];
    const float* b_g    = (const float*)d_in[5];
    const float* fbase  = (const float*)d_in[6];
    const float* W_out  = (const float*)d_in[7];
    float* out = (float*)d_out;

    float *gx, *xbc, *fg, *xs;
    cudaGetSymbolAddress((void**)&gx,  g_gx);
    cudaGetSymbolAddress((void**)&xbc, g_xbc);
    cudaGetSymbolAddress((void**)&fg,  g_fg);
    cudaGetSymbolAddress((void**)&xs,  g_xs);

    cudaFuncSetAttribute(gemm_mma<false>, cudaFuncAttributeMaxDynamicSharedMemorySize, GEMM_SMEM);
    cudaFuncSetAttribute(gemm_mma<true>,  cudaFuncAttributeMaxDynamicSharedMemorySize, GEMM_SMEM);

    const long long tot = (long long)M_ * H_;
    const int EB = 256;
    const int eg = (int)((tot + EB - 1) / EB);

    // 1) gx = x @ W_in^T      [16384 x 3072, K=1024]
    gemm_mma<false><<<dim3(G2H/128, M_/128), 256, GEMM_SMEM>>>(x, W_in, nullptr, gx, D_, D_, D_, G2H);
    // 2) depthwise causal conv on B-half
    conv_kernel<<<eg, EB>>>(conv_w, conv_b);
    // 3) fg = xbc @ W_g^T + b_g   [16384 x 3072, K=1536]
    gemm_mma<true><<<dim3(G2H/128, M_/128), 256, GEMM_SMEM>>>(xbc, W_g, b_g, fg, H_, H_, H_, G2H);
    // 4) alpha/xs + gelu(gate)
    ew_kernel<<<eg, EB>>>(fbase);
    // 5) linear scan (3 phases)
    scan_p1<<<dim3(H_/128, NC, N_), 128>>>();
    scan_p2<<<dim3(H_/128, N_), 128>>>();
    scan_p3<<<dim3(H_/128, NC, N_), 128>>>();
    // 6) out = (gelu(gate)*h) @ W_out^T   [16384 x 1024, K=1536]
    gemm_mma<false><<<dim3(D_/128, M_/128), 256, GEMM_SMEM>>>(xs, W_out, nullptr, out, H_, H_, H_, D_);
}